// round 4
// baseline (speedup 1.0000x reference)
#include <cuda_runtime.h>
#include <cmath>

#define CF 22
#define IPAD 24
#define KPAD 24
#define NM 9
#define TILE_W 16
#define TILE_H 8
#define NT 128
#define FT_W 17
#define FT_H 17
#define FT_STRIDE 24

typedef unsigned long long ull;

// Prep outputs (device globals). W is copied to shared per block; K is read
// directly from global via warp-uniform LDG (L1-resident, 1 wavefront/load).
__device__ float gWtp[CF * CF * IPAD];  // [k][j][i24]
__device__ float gK[NM * CF * KPAD];    // [m][i][k24]

// ---- packed f32x2 helpers (Blackwell FFMA2 path; only reachable via PTX) ----
__device__ __forceinline__ ull pk2(float lo, float hi) {
    ull r; asm("mov.b64 %0, {%1,%2};" : "=l"(r) : "f"(lo), "f"(hi)); return r;
}
__device__ __forceinline__ void upk2(ull v, float& a, float& b) {
    asm("mov.b64 {%0,%1}, %2;" : "=f"(a), "=f"(b) : "l"(v));
}
__device__ __forceinline__ ull pdup(float x) {
    ull r; asm("mov.b64 %0, {%1,%1};" : "=l"(r) : "f"(x)); return r;
}
__device__ __forceinline__ ull pfma(ull a, ull b, ull c) {
    ull r; asm("fma.rn.f32x2 %0, %1, %2, %3;" : "=l"(r) : "l"(a), "l"(b), "l"(c)); return r;
}
__device__ __forceinline__ ull pmul(ull a, ull b) {
    ull r; asm("mul.rn.f32x2 %0, %1, %2;" : "=l"(r) : "l"(a), "l"(b)); return r;
}
__device__ __forceinline__ ull padd(ull a, ull b) {
    ull r; asm("add.rn.f32x2 %0, %1, %2;" : "=l"(r) : "l"(a), "l"(b)); return r;
}

// ============================================================================
// Prep: fold learned weights into Wtp and the 9 context matrices.
// m: 0:K0+K1+K2+K3  1:K0+K2  2:K0+K1  3:K0  4:K1+K3  5:K1  6:K2+K3  7:K2  8:K3
// ============================================================================
__global__ void prep_kernel(const float* __restrict__ sh,
                            const float* __restrict__ cg_agg,
                            const float* __restrict__ cg_tp,
                            const float* __restrict__ w_agg,
                            const float* __restrict__ w_tp) {
    int gtid = blockIdx.x * blockDim.x + threadIdx.x;
    int nthr = gridDim.x * blockDim.x;
    for (int idx = gtid; idx < CF * CF * IPAD; idx += nthr) {
        int k = idx / (CF * IPAD);
        int r = idx - k * CF * IPAD;
        int j = r / IPAD;
        int i = r - j * IPAD;
        float v = 0.f;
        if (i < CF) {
            #pragma unroll
            for (int p = 0; p < 8; p++)
                v += w_tp[p] * cg_tp[((p * CF + i) * CF + j) * CF + k];
        }
        gWtp[idx] = v;
    }
    for (int idx = gtid; idx < CF * KPAD; idx += nthr) {
        int i = idx / KPAD;
        int k = idx - i * KPAD;
        float K0 = 0.f, K1 = 0.f, K2 = 0.f, K3 = 0.f;
        if (k < CF) {
            #pragma unroll
            for (int s = 0; s < 6; s++) {
                float wa = 0.f;
                #pragma unroll
                for (int p = 0; p < 6; p++)
                    wa += w_agg[p] * cg_agg[((p * CF + i) * 6 + s) * CF + k];
                K0 += wa * sh[0 * 6 + s];
                K1 += wa * sh[1 * 6 + s];
                K2 += wa * sh[2 * 6 + s];
                K3 += wa * sh[3 * 6 + s];
            }
        }
        gK[(0 * CF + i) * KPAD + k] = K0 + K1 + K2 + K3;
        gK[(1 * CF + i) * KPAD + k] = K0 + K2;
        gK[(2 * CF + i) * KPAD + k] = K0 + K1;
        gK[(3 * CF + i) * KPAD + k] = K0;
        gK[(4 * CF + i) * KPAD + k] = K1 + K3;
        gK[(5 * CF + i) * KPAD + k] = K1;
        gK[(6 * CF + i) * KPAD + k] = K2 + K3;
        gK[(7 * CF + i) * KPAD + k] = K2;
        gK[(8 * CF + i) * KPAD + k] = K3;
    }
}

// Context accumulation: warp-uniform global loads of K (L1-resident)
template <int CAT>
__device__ __forceinline__ void ctx_pass(ull (&ctx2)[4][11], const float* __restrict__ src, int m) {
    #pragma unroll 2
    for (int i = 0; i < CF; i++) {
        ull fi2 = pdup(src[i]);
        const ulonglong2* __restrict__ row2 =
            reinterpret_cast<const ulonglong2*>(gK + (m * CF + i) * KPAD);
        #pragma unroll
        for (int c = 0; c < 5; c++) {
            ulonglong2 t = row2[c];
            ctx2[CAT][2 * c]     = pfma(fi2, t.x, ctx2[CAT][2 * c]);
            ctx2[CAT][2 * c + 1] = pfma(fi2, t.y, ctx2[CAT][2 * c + 1]);
        }
        ull t10 = reinterpret_cast<const ull*>(gK + (m * CF + i) * KPAD)[10];
        ctx2[CAT][10] = pfma(fi2, t10, ctx2[CAT][10]);
    }
}

// ============================================================================
// Main kernel: 1 thread per low-res pixel; 16x8 tile per block.
// smem/block = W (46.5KB) + shared region (27.7KB: ftile, later out stage)
//            = 74.2KB -> 3 blocks/SM = 12 warps (was 8).
// ============================================================================
__global__ void __launch_bounds__(NT, 3)
main_kernel(const float* __restrict__ f4, const float* __restrict__ f6,
            float* __restrict__ out, int H, int W) {
    extern __shared__ float smem[];
    float* sW = smem;                        // CF*CF*IPAD = 11616 floats
    float* sh_region = smem + CF * CF * IPAD; // 6936 floats (ftile / out stage)
    const int tid = threadIdx.x;

    for (int idx = tid; idx < CF * CF * IPAD; idx += NT) sW[idx] = gWtp[idx];

    const int tiles_x = W / TILE_W;
    const int tx0 = (blockIdx.x % tiles_x) * TILE_W;
    const int ty0 = (blockIdx.x / tiles_x) * TILE_H;
    const int lx = tid % TILE_W;
    const int ly = tid / TILE_W;

    // ---- cooperative feature tile: (TILE_H+1) x (TILE_W+1) px, edge-clamped ----
    float* ftile = sh_region;  // [FT_H][FT_W][FT_STRIDE], uses 9x17 rows here
    {
        const int NPX = (TILE_H + 1) * (TILE_W + 1);  // 9*17 = 153
        for (int idx = tid; idx < NPX * CF; idx += NT) {
            int p = idx / CF;
            int ch = idx - p * CF;
            int pyy = p / (TILE_W + 1);
            int pxx = p - pyy * (TILE_W + 1);
            int gw = min(tx0 + pxx, W - 1);
            int gh = min(ty0 + pyy, H - 1);
            size_t g = (size_t)gh * W + gw;
            ftile[(pyy * FT_W + pxx) * FT_STRIDE + ch] =
                (ch < 9) ? f4[g * 9 + ch] : f6[g * 13 + (ch - 9)];
        }
    }
    __syncthreads();

    const float* fme = ftile + (ly * FT_W + lx) * FT_STRIDE;
    const float* fR  = ftile + (ly * FT_W + lx + 1) * FT_STRIDE;
    const float* fD  = ftile + ((ly + 1) * FT_W + lx) * FT_STRIDE;
    const float* fX  = ftile + ((ly + 1) * FT_W + lx + 1) * FT_STRIDE;

    // self features -> packed regs
    ull f2[11];
    {
        #pragma unroll
        for (int kk = 0; kk < 11; kk++) f2[kk] = pk2(fme[2 * kk], fme[2 * kk + 1]);
    }

    // ---- 4 context vectors (cat 0:interior 1:right-edge 2:bottom-edge 3:corner) ----
    ull ctx2[4][11];
    #pragma unroll
    for (int c4 = 0; c4 < 4; c4++)
        #pragma unroll
        for (int kk = 0; kk < 11; kk++) ctx2[c4][kk] = 0ULL;

    ctx_pass<0>(ctx2, fme, 0);
    ctx_pass<1>(ctx2, fme, 1);
    ctx_pass<2>(ctx2, fme, 2);
    ctx_pass<3>(ctx2, fme, 3);
    ctx_pass<1>(ctx2, fR, 4);
    ctx_pass<3>(ctx2, fR, 5);
    ctx_pass<2>(ctx2, fD, 6);
    ctx_pass<3>(ctx2, fD, 7);
    ctx_pass<3>(ctx2, fX, 8);

    float ctx[4][CF];
    #pragma unroll
    for (int c4 = 0; c4 < 4; c4++)
        #pragma unroll
        for (int kk = 0; kk < 11; kk++) {
            float a, b;
            upk2(ctx2[c4][kk], a, b);
            ctx[c4][2 * kk] = a;
            ctx[c4][2 * kk + 1] = b;
        }
    __syncthreads();  // ftile consumed; region can be reused for out staging

    const int Wr = W * 4;
    const ulonglong2* sW2 = (const ulonglong2*)sW;

    // ================= phase 1: k = 0..8 (out4 channels) =================
    {
        float* stg = sh_region;  // [NT][37]
        float* myst = stg + tid * 37;
        for (int k = 0; k < 9; k++) {
            ull o0 = 0ULL, o1 = 0ULL, o2a = 0ULL, o3 = 0ULL;
            const ulonglong2* wbase = sW2 + k * (CF * 6);
            #pragma unroll 2
            for (int j = 0; j < CF; j++) {
                const ulonglong2* wr = wbase + j * 6;
                ulonglong2 t0 = wr[0], t1 = wr[1], t2 = wr[2];
                ull va = pmul(f2[0], t0.x);
                ull vb = pmul(f2[1], t0.y);
                va = pfma(f2[2], t1.x, va);
                vb = pfma(f2[3], t1.y, vb);
                va = pfma(f2[4], t2.x, va);
                vb = pfma(f2[5], t2.y, vb);
                ulonglong2 t3 = wr[3], t4 = wr[4], t5 = wr[5];
                va = pfma(f2[6], t3.x, va);
                vb = pfma(f2[7], t3.y, vb);
                va = pfma(f2[8], t4.x, va);
                vb = pfma(f2[9], t4.y, vb);
                va = pfma(f2[10], t5.x, va);
                ull v = padd(va, vb);
                o0  = pfma(pdup(ctx[0][j]), v, o0);
                o1  = pfma(pdup(ctx[1][j]), v, o1);
                o2a = pfma(pdup(ctx[2][j]), v, o2a);
                o3  = pfma(pdup(ctx[3][j]), v, o3);
            }
            float a, b;
            upk2(o0, a, b);  myst[0 * 9 + k] = a + b;
            upk2(o1, a, b);  myst[1 * 9 + k] = a + b;
            upk2(o2a, a, b); myst[2 * 9 + k] = a + b;
            upk2(o3, a, b);  myst[3 * 9 + k] = a + b;
        }
        __syncthreads();
        // drain out4: 64 px * 9 floats = 144 float4 per hi-res row
        const int QR = TILE_W * 4 * 9 / 4;  // 144
        for (int idx = tid; idx < TILE_H * 4 * QR; idx += NT) {
            int y = idx / QR;
            int q = idx - y * QR;
            int a = y & 3;
            int py = y >> 2;
            int e = q * 4;
            float4 v;
            float* vv = (float*)&v;
            #pragma unroll
            for (int t = 0; t < 4; t++) {
                int ee = e + t;
                int px = ee / 9;
                int c = ee - px * 9;
                int b = px & 3;
                int lxr = px >> 2;
                int cat = (a < 3) ? ((b < 3) ? 0 : 1) : ((b < 3) ? 2 : 3);
                vv[t] = stg[(py * TILE_W + lxr) * 37 + cat * 9 + c]
                      + f4[(size_t)((ty0 + py) * W + tx0 + lxr) * 9 + c];  // residual
            }
            int gy = ty0 * 4 + y;
            float4* dst = (float4*)(out + ((size_t)gy * Wr + (size_t)tx0 * 4) * 9);
            dst[q] = v;
        }
        __syncthreads();
    }

    // ================= phase 2: k = 9..21 (out6 channels) =================
    {
        float* stg = sh_region;  // [NT][53]
        float* myst = stg + tid * 53;
        for (int k = 9; k < CF; k++) {
            ull o0 = 0ULL, o1 = 0ULL, o2a = 0ULL, o3 = 0ULL;
            const ulonglong2* wbase = sW2 + k * (CF * 6);
            #pragma unroll 2
            for (int j = 0; j < CF; j++) {
                const ulonglong2* wr = wbase + j * 6;
                ulonglong2 t0 = wr[0], t1 = wr[1], t2 = wr[2];
                ull va = pmul(f2[0], t0.x);
                ull vb = pmul(f2[1], t0.y);
                va = pfma(f2[2], t1.x, va);
                vb = pfma(f2[3], t1.y, vb);
                va = pfma(f2[4], t2.x, va);
                vb = pfma(f2[5], t2.y, vb);
                ulonglong2 t3 = wr[3], t4 = wr[4], t5 = wr[5];
                va = pfma(f2[6], t3.x, va);
                vb = pfma(f2[7], t3.y, vb);
                va = pfma(f2[8], t4.x, va);
                vb = pfma(f2[9], t4.y, vb);
                va = pfma(f2[10], t5.x, va);
                ull v = padd(va, vb);
                o0  = pfma(pdup(ctx[0][j]), v, o0);
                o1  = pfma(pdup(ctx[1][j]), v, o1);
                o2a = pfma(pdup(ctx[2][j]), v, o2a);
                o3  = pfma(pdup(ctx[3][j]), v, o3);
            }
            int kc = k - 9;
            float a, b;
            upk2(o0, a, b);  myst[0 * 13 + kc] = a + b;
            upk2(o1, a, b);  myst[1 * 13 + kc] = a + b;
            upk2(o2a, a, b); myst[2 * 13 + kc] = a + b;
            upk2(o3, a, b);  myst[3 * 13 + kc] = a + b;
        }
        __syncthreads();
        // drain out6: 64 px * 13 floats = 208 float4 per hi-res row
        const size_t N9 = (size_t)H * W * 16 * 9;
        const int QR = TILE_W * 4 * 13 / 4;  // 208
        for (int idx = tid; idx < TILE_H * 4 * QR; idx += NT) {
            int y = idx / QR;
            int q = idx - y * QR;
            int a = y & 3;
            int py = y >> 2;
            int e = q * 4;
            float4 v;
            float* vv = (float*)&v;
            #pragma unroll
            for (int t = 0; t < 4; t++) {
                int ee = e + t;
                int px = ee / 13;
                int c = ee - px * 13;
                int b = px & 3;
                int lxr = px >> 2;
                int cat = (a < 3) ? ((b < 3) ? 0 : 1) : ((b < 3) ? 2 : 3);
                vv[t] = stg[(py * TILE_W + lxr) * 53 + cat * 13 + c]
                      + f6[(size_t)((ty0 + py) * W + tx0 + lxr) * 13 + c];  // residual
            }
            int gy = ty0 * 4 + y;
            float4* dst = (float4*)(out + N9 + ((size_t)gy * Wr + (size_t)tx0 * 4) * 13);
            dst[q] = v;
        }
    }
}

extern "C" void kernel_launch(void* const* d_in, const int* in_sizes, int n_in,
                              void* d_out, int out_size) {
    const float* f4     = (const float*)d_in[0];
    const float* f6     = (const float*)d_in[1];
    const float* sh     = (const float*)d_in[2];
    const float* cg_agg = (const float*)d_in[3];
    const float* cg_tp  = (const float*)d_in[4];
    const float* w_agg  = (const float*)d_in[5];
    const float* w_tp   = (const float*)d_in[6];
    float* out = (float*)d_out;

    int HW = in_sizes[0] / 9;
    int W = (int)(sqrt((double)HW) + 0.5);
    int H = HW / W;

    prep_kernel<<<96, 128>>>(sh, cg_agg, cg_tp, w_agg, w_tp);

    const int region = FT_H * FT_W * FT_STRIDE;  // 6936 >= max(NT*37, NT*53)
    int smemB = (CF * CF * IPAD + region) * (int)sizeof(float);
    cudaFuncSetAttribute(main_kernel, cudaFuncAttributeMaxDynamicSharedMemorySize, smemB);
    int nblocks = HW / NT;
    main_kernel<<<nblocks, NT, smemB>>>(f4, f6, out, H, W);
}

// round 5
// speedup vs baseline: 1.7338x; 1.7338x over previous
#include <cuda_runtime.h>
#include <cmath>

#define CF 22
#define IPAD 24
#define KPAD 24
#define NM 9
#define TILE_W 16
#define TILE_H 8
#define NT 128

typedef unsigned long long ull;

// Precomputed weighted tensors (prep kernel output)
__device__ float gWtp[CF * CF * IPAD];  // [k][j][i24]
__device__ float gK[NM * CF * KPAD];    // [m][i][k24]

// ---- packed f32x2 helpers (Blackwell FFMA2 path; only reachable via PTX) ----
__device__ __forceinline__ ull pk2(float lo, float hi) {
    ull r; asm("mov.b64 %0, {%1,%2};" : "=l"(r) : "f"(lo), "f"(hi)); return r;
}
__device__ __forceinline__ void upk2(ull v, float& a, float& b) {
    asm("mov.b64 {%0,%1}, %2;" : "=f"(a), "=f"(b) : "l"(v));
}
__device__ __forceinline__ ull pdup(float x) {
    ull r; asm("mov.b64 %0, {%1,%1};" : "=l"(r) : "f"(x)); return r;
}
__device__ __forceinline__ ull pfma(ull a, ull b, ull c) {
    ull r; asm("fma.rn.f32x2 %0, %1, %2, %3;" : "=l"(r) : "l"(a), "l"(b), "l"(c)); return r;
}
__device__ __forceinline__ ull pmul(ull a, ull b) {
    ull r; asm("mul.rn.f32x2 %0, %1, %2;" : "=l"(r) : "l"(a), "l"(b)); return r;
}
__device__ __forceinline__ ull padd(ull a, ull b) {
    ull r; asm("add.rn.f32x2 %0, %1, %2;" : "=l"(r) : "l"(a), "l"(b)); return r;
}

// ============================================================================
// Prep: fold learned weights into Wtp and the 9 context matrices.
// m: 0:K0+K1+K2+K3  1:K0+K2  2:K0+K1  3:K0  4:K1+K3  5:K1  6:K2+K3  7:K2  8:K3
// ============================================================================
__global__ void prep_kernel(const float* __restrict__ sh,
                            const float* __restrict__ cg_agg,
                            const float* __restrict__ cg_tp,
                            const float* __restrict__ w_agg,
                            const float* __restrict__ w_tp) {
    int gtid = blockIdx.x * blockDim.x + threadIdx.x;
    int nthr = gridDim.x * blockDim.x;
    for (int idx = gtid; idx < CF * CF * IPAD; idx += nthr) {
        int k = idx / (CF * IPAD);
        int r = idx - k * CF * IPAD;
        int j = r / IPAD;
        int i = r - j * IPAD;
        float v = 0.f;
        if (i < CF) {
            #pragma unroll
            for (int p = 0; p < 8; p++)
                v += w_tp[p] * cg_tp[((p * CF + i) * CF + j) * CF + k];
        }
        gWtp[idx] = v;
    }
    for (int idx = gtid; idx < CF * KPAD; idx += nthr) {
        int i = idx / KPAD;
        int k = idx - i * KPAD;
        float K0 = 0.f, K1 = 0.f, K2 = 0.f, K3 = 0.f;
        if (k < CF) {
            #pragma unroll
            for (int s = 0; s < 6; s++) {
                float wa = 0.f;
                #pragma unroll
                for (int p = 0; p < 6; p++)
                    wa += w_agg[p] * cg_agg[((p * CF + i) * 6 + s) * CF + k];
                K0 += wa * sh[0 * 6 + s];
                K1 += wa * sh[1 * 6 + s];
                K2 += wa * sh[2 * 6 + s];
                K3 += wa * sh[3 * 6 + s];
            }
        }
        gK[(0 * CF + i) * KPAD + k] = K0 + K1 + K2 + K3;
        gK[(1 * CF + i) * KPAD + k] = K0 + K2;
        gK[(2 * CF + i) * KPAD + k] = K0 + K1;
        gK[(3 * CF + i) * KPAD + k] = K0;
        gK[(4 * CF + i) * KPAD + k] = K1 + K3;
        gK[(5 * CF + i) * KPAD + k] = K1;
        gK[(6 * CF + i) * KPAD + k] = K2 + K3;
        gK[(7 * CF + i) * KPAD + k] = K2;
        gK[(8 * CF + i) * KPAD + k] = K3;
    }
}

// Context accumulation pass: ctx2[CAT][*] += src[i] * sK[m][i][*]
// All ctx2 indices are static (template CAT + unrolled c) -> stays in registers.
template <int CAT>
__device__ __forceinline__ void ctx_pass(ull (&ctx2)[4][11], const ulonglong2* sK2,
                                         const float* src, int m) {
    #pragma unroll 2
    for (int i = 0; i < CF; i++) {
        ull fi2 = pdup(src[i]);
        const ulonglong2* row = sK2 + (m * CF + i) * 6;
        #pragma unroll
        for (int c = 0; c < 5; c++) {
            ulonglong2 t = row[c];
            ctx2[CAT][2 * c]     = pfma(fi2, t.x, ctx2[CAT][2 * c]);
            ctx2[CAT][2 * c + 1] = pfma(fi2, t.y, ctx2[CAT][2 * c + 1]);
        }
        ull t10 = row[5].x;
        ctx2[CAT][10] = pfma(fi2, t10, ctx2[CAT][10]);
    }
}

// ============================================================================
// Main kernel: one thread per low-res pixel; 16x8 low-res tile per block.
// Shared: sW (45.4KB) + sK (18.6KB) + stage (44.5KB) = 108.5 KB -> 2 blocks/SM.
// Critical: j-loop in the bilinear phase is FULLY unrolled so ctx[cat][j]
// is always statically indexed (otherwise ctx demotes to local memory).
// ============================================================================
__global__ void __launch_bounds__(NT, 2)
main_kernel(const float* __restrict__ f4, const float* __restrict__ f6,
            float* __restrict__ out, int H, int W) {
    extern __shared__ float smem[];
    float* sW = smem;                      // CF*CF*IPAD
    float* sK = smem + CF * CF * IPAD;     // NM*CF*KPAD
    float* stg = sK + NM * CF * KPAD;      // NT*89 (stride 89 -> conflict-free)
    const int tid = threadIdx.x;

    for (int idx = tid; idx < CF * CF * IPAD; idx += NT) sW[idx] = gWtp[idx];
    for (int idx = tid; idx < NM * CF * KPAD; idx += NT) sK[idx] = gK[idx];
    __syncthreads();

    const int tiles_x = W / TILE_W;
    const int tx0 = (blockIdx.x % tiles_x) * TILE_W;
    const int ty0 = (blockIdx.x / tiles_x) * TILE_H;
    const int lx = tid % TILE_W;
    const int ly = tid / TILE_W;
    const int w0 = tx0 + lx;
    const int h0 = ty0 + ly;
    const int wR = min(w0 + 1, W - 1);
    const int hD = min(h0 + 1, H - 1);
    const int p00 = h0 * W + w0;
    const int p01 = h0 * W + wR;
    const int p10 = hD * W + w0;
    const int p11 = hD * W + wR;

    // ---- preload features: self -> packed regs, all 4 sources -> per-thread stage ----
    float* myst = stg + tid * 89;
    ull f2[11];
    {
        float xv[CF];
        #pragma unroll
        for (int c = 0; c < CF; c++) {
            xv[c] = (c < 9) ? f4[p00 * 9 + c] : f6[p00 * 13 + (c - 9)];
            myst[c] = xv[c];
        }
        #pragma unroll
        for (int kk = 0; kk < 11; kk++) f2[kk] = pk2(xv[2 * kk], xv[2 * kk + 1]);
        #pragma unroll
        for (int c = 0; c < CF; c++) {
            myst[1 * CF + c] = (c < 9) ? f4[p01 * 9 + c] : f6[p01 * 13 + (c - 9)];
            myst[2 * CF + c] = (c < 9) ? f4[p10 * 9 + c] : f6[p10 * 13 + (c - 9)];
            myst[3 * CF + c] = (c < 9) ? f4[p11 * 9 + c] : f6[p11 * 13 + (c - 9)];
        }
    }

    // ---- 4 context vectors (cat 0:interior 1:right-edge 2:bottom-edge 3:corner) ----
    ull ctx2[4][11];
    #pragma unroll
    for (int c4 = 0; c4 < 4; c4++)
        #pragma unroll
        for (int kk = 0; kk < 11; kk++) ctx2[c4][kk] = 0ULL;

    const ulonglong2* sK2 = (const ulonglong2*)sK;
    ctx_pass<0>(ctx2, sK2, myst, 0);
    ctx_pass<1>(ctx2, sK2, myst, 1);
    ctx_pass<2>(ctx2, sK2, myst, 2);
    ctx_pass<3>(ctx2, sK2, myst, 3);
    ctx_pass<1>(ctx2, sK2, myst + CF, 4);
    ctx_pass<3>(ctx2, sK2, myst + CF, 5);
    ctx_pass<2>(ctx2, sK2, myst + 2 * CF, 6);
    ctx_pass<3>(ctx2, sK2, myst + 2 * CF, 7);
    ctx_pass<3>(ctx2, sK2, myst + 3 * CF, 8);

    float ctx[4][CF];
    #pragma unroll
    for (int c4 = 0; c4 < 4; c4++)
        #pragma unroll
        for (int kk = 0; kk < 11; kk++) {
            float a, b;
            upk2(ctx2[c4][kk], a, b);
            ctx[c4][2 * kk] = a;
            ctx[c4][2 * kk + 1] = b;
        }

    // ---- bilinear: out_cat[k] = sum_j ctx[cat][j] * (sum_i f[i] * W[k][j][i]) ----
    const ulonglong2* sW2 = (const ulonglong2*)sW;
    #pragma unroll 1
    for (int k = 0; k < CF; k++) {
        ull o0 = 0ULL, o1 = 0ULL, o2a = 0ULL, o3 = 0ULL;
        const ulonglong2* wbase = sW2 + k * (CF * 6);
        #pragma unroll
        for (int j = 0; j < CF; j++) {
            const ulonglong2* wr = wbase + j * 6;
            ulonglong2 t0 = wr[0], t1 = wr[1], t2 = wr[2];
            ull va = pmul(f2[0], t0.x);
            ull vb = pmul(f2[1], t0.y);
            va = pfma(f2[2], t1.x, va);
            vb = pfma(f2[3], t1.y, vb);
            va = pfma(f2[4], t2.x, va);
            vb = pfma(f2[5], t2.y, vb);
            ulonglong2 t3 = wr[3], t4 = wr[4];
            ull t10 = wr[5].x;
            va = pfma(f2[6], t3.x, va);
            vb = pfma(f2[7], t3.y, vb);
            va = pfma(f2[8], t4.x, va);
            vb = pfma(f2[9], t4.y, vb);
            va = pfma(f2[10], t10, va);
            ull v = padd(va, vb);
            o0  = pfma(pdup(ctx[0][j]), v, o0);   // static j -> register refs
            o1  = pfma(pdup(ctx[1][j]), v, o1);
            o2a = pfma(pdup(ctx[2][j]), v, o2a);
            o3  = pfma(pdup(ctx[3][j]), v, o3);
        }
        float a, b;
        upk2(o0, a, b);  myst[0 * CF + k] = a + b;  // sources consumed: reuse slots
        upk2(o1, a, b);  myst[1 * CF + k] = a + b;
        upk2(o2a, a, b); myst[2 * CF + k] = a + b;
        upk2(o3, a, b);  myst[3 * CF + k] = a + b;
    }
    __syncthreads();

    // ---- coalesced write phase: contiguous float4 stores over hi-res rows ----
    const int Wr = W * 4;
    {   // out4: 64 px * 9 floats = 144 float4 per hi-res row
        const int QR = TILE_W * 4 * 9 / 4;  // 144
        for (int idx = tid; idx < TILE_H * 4 * QR; idx += NT) {
            int y = idx / QR;
            int q = idx - y * QR;
            int a = y & 3;
            int py = y >> 2;
            int e = q * 4;
            float4 v;
            float* vv = (float*)&v;
            #pragma unroll
            for (int t = 0; t < 4; t++) {
                int ee = e + t;
                int px = ee / 9;
                int c = ee - px * 9;
                int b = px & 3;
                int lxr = px >> 2;
                int cat = (a < 3) ? ((b < 3) ? 0 : 1) : ((b < 3) ? 2 : 3);
                vv[t] = stg[(py * TILE_W + lxr) * 89 + cat * CF + c]
                      + f4[(size_t)((ty0 + py) * W + tx0 + lxr) * 9 + c];  // residual
            }
            int gy = ty0 * 4 + y;
            float4* dst = (float4*)(out + ((size_t)gy * Wr + (size_t)tx0 * 4) * 9);
            dst[q] = v;
        }
    }
    {   // out6: 64 px * 13 floats = 208 float4 per hi-res row
        const size_t N9 = (size_t)H * W * 16 * 9;
        const int QR = TILE_W * 4 * 13 / 4;  // 208
        for (int idx = tid; idx < TILE_H * 4 * QR; idx += NT) {
            int y = idx / QR;
            int q = idx - y * QR;
            int a = y & 3;
            int py = y >> 2;
            int e = q * 4;
            float4 v;
            float* vv = (float*)&v;
            #pragma unroll
            for (int t = 0; t < 4; t++) {
                int ee = e + t;
                int px = ee / 13;
                int c = ee - px * 13;
                int b = px & 3;
                int lxr = px >> 2;
                int cat = (a < 3) ? ((b < 3) ? 0 : 1) : ((b < 3) ? 2 : 3);
                vv[t] = stg[(py * TILE_W + lxr) * 89 + cat * CF + 9 + c]
                      + f6[(size_t)((ty0 + py) * W + tx0 + lxr) * 13 + c];  // residual
            }
            int gy = ty0 * 4 + y;
            float4* dst = (float4*)(out + N9 + ((size_t)gy * Wr + (size_t)tx0 * 4) * 13);
            dst[q] = v;
        }
    }
}

extern "C" void kernel_launch(void* const* d_in, const int* in_sizes, int n_in,
                              void* d_out, int out_size) {
    const float* f4     = (const float*)d_in[0];
    const float* f6     = (const float*)d_in[1];
    const float* sh     = (const float*)d_in[2];
    const float* cg_agg = (const float*)d_in[3];
    const float* cg_tp  = (const float*)d_in[4];
    const float* w_agg  = (const float*)d_in[5];
    const float* w_tp   = (const float*)d_in[6];
    float* out = (float*)d_out;

    int HW = in_sizes[0] / 9;
    int W = (int)(sqrt((double)HW) + 0.5);
    int H = HW / W;

    prep_kernel<<<96, 128>>>(sh, cg_agg, cg_tp, w_agg, w_tp);

    int smemB = (CF * CF * IPAD + NM * CF * KPAD + NT * 89) * (int)sizeof(float);
    cudaFuncSetAttribute(main_kernel, cudaFuncAttributeMaxDynamicSharedMemorySize, smemB);
    int nblocks = HW / NT;
    main_kernel<<<nblocks, NT, smemB>>>(f4, f6, out, H, W);
}